// round 1
// baseline (speedup 1.0000x reference)
#include <cuda_runtime.h>
#include <math.h>

#define POOL   100
#define N_TASKS 10
#define P_LEN    8
#define EMB_D  768
#define BATCH  512
#define NBLK   197

// scratch (no cudaMalloc allowed)
__device__ float g_diag[POOL * EMB_D];   // 300 KB
__device__ float g_sim[BATCH * POOL];    // 200 KB

// ---------------------------------------------------------------------------
// Kernel 1: diag[k][d] = sum_l e_p[k][l][d]^2   (k < task_end)
// ---------------------------------------------------------------------------
__global__ void diag_kernel(const float* __restrict__ e_p,
                            const int* __restrict__ task_id) {
    const int te = (task_id[0] + 1) * (POOL / N_TASKS);
    const int i = blockIdx.x * blockDim.x + threadIdx.x;
    if (i >= te * EMB_D) return;
    const int k = i / EMB_D;
    const int d = i - k * EMB_D;
    const float* base = e_p + (size_t)k * P_LEN * EMB_D + d;
    float s = 0.f;
#pragma unroll
    for (int l = 0; l < P_LEN; ++l) {
        float v = base[(size_t)l * EMB_D];
        s = fmaf(v, v, s);
    }
    g_diag[i] = s;
}

// ---------------------------------------------------------------------------
// Kernel 2: sim[b][k] = S_ad / (max(sqrt(S_a),eps) * max(sqrt(S_add),eps))
//   a = xq[b, POOL-te+k, :] * e_a[k, :]
//   S_a = sum a^2, S_ad = sum a^2*diag, S_add = sum a^2*diag^2
// one block per (b, k); 256 threads reduce over EMB_D=768
// ---------------------------------------------------------------------------
__global__ void sim_kernel(const float* __restrict__ x_querry,
                           const float* __restrict__ e_a,
                           const int* __restrict__ task_id) {
    const int te = (task_id[0] + 1) * (POOL / N_TASKS);
    const int b = blockIdx.x;
    const int k = blockIdx.y;
    if (k >= te) return;

    const float* __restrict__ x  = x_querry + ((size_t)b * POOL + (POOL - te + k)) * EMB_D;
    const float* __restrict__ ea = e_a   + (size_t)k * EMB_D;
    const float* __restrict__ dg = g_diag + (size_t)k * EMB_D;

    float sa = 0.f, sad = 0.f, sadd = 0.f;
    for (int d = threadIdx.x; d < EMB_D; d += blockDim.x) {
        float a  = x[d] * ea[d];
        float a2 = a * a;
        float dd = dg[d];
        sa   = fmaf(a2, 1.0f, sa);
        sad  = fmaf(a2, dd, sad);
        sadd = fmaf(a2 * dd, dd, sadd);
    }

    // warp reduce
#pragma unroll
    for (int off = 16; off > 0; off >>= 1) {
        sa   += __shfl_down_sync(0xffffffffu, sa,   off);
        sad  += __shfl_down_sync(0xffffffffu, sad,  off);
        sadd += __shfl_down_sync(0xffffffffu, sadd, off);
    }
    __shared__ float sh[3][8];
    const int wid = threadIdx.x >> 5;
    const int lid = threadIdx.x & 31;
    if (lid == 0) { sh[0][wid] = sa; sh[1][wid] = sad; sh[2][wid] = sadd; }
    __syncthreads();
    if (wid == 0) {
        sa   = (lid < 8) ? sh[0][lid] : 0.f;
        sad  = (lid < 8) ? sh[1][lid] : 0.f;
        sadd = (lid < 8) ? sh[2][lid] : 0.f;
#pragma unroll
        for (int off = 4; off > 0; off >>= 1) {
            sa   += __shfl_down_sync(0xffffffffu, sa,   off);
            sad  += __shfl_down_sync(0xffffffffu, sad,  off);
            sadd += __shfl_down_sync(0xffffffffu, sadd, off);
        }
        if (lid == 0) {
            float na  = fmaxf(sqrtf(sa),   1e-12f);
            float nad = fmaxf(sqrtf(sadd), 1e-12f);
            g_sim[b * POOL + k] = sad / (na * nad);
        }
    }
}

// ---------------------------------------------------------------------------
// Kernel 3: int_pmt[b,l,:] = sum_k sim[b,k] * e_p[k,l,:]; split key/value
// one block per b; float4 vectorized; e_p (245 KB) stays resident in L2
// ---------------------------------------------------------------------------
__global__ void pmt_kernel(const float* __restrict__ e_p,
                           const int* __restrict__ task_id,
                           float* __restrict__ out) {
    const int te = (task_id[0] + 1) * (POOL / N_TASKS);
    const int b = blockIdx.x;

    __shared__ float sim_s[POOL];
    if (threadIdx.x < te) sim_s[threadIdx.x] = g_sim[b * POOL + threadIdx.x];
    __syncthreads();

    const int D4 = EMB_D / 4;            // 192
    const int NV = P_LEN * D4;           // 1536 float4 per batch row
    const float4* __restrict__ ep4 = (const float4*)e_p;
    float4* __restrict__ out4 = (float4*)out;
    const size_t half_elems4 = (size_t)BATCH * (P_LEN / 2) * D4;

    for (int v = threadIdx.x; v < NV; v += blockDim.x) {
        float4 acc = make_float4(0.f, 0.f, 0.f, 0.f);
        for (int k = 0; k < te; ++k) {
            const float s = sim_s[k];
            const float4 e = ep4[(size_t)k * NV + v];
            acc.x = fmaf(s, e.x, acc.x);
            acc.y = fmaf(s, e.y, acc.y);
            acc.z = fmaf(s, e.z, acc.z);
            acc.w = fmaf(s, e.w, acc.w);
        }
        const int l  = v / D4;
        const int d4 = v - l * D4;
        size_t off;
        if (l < P_LEN / 2) {
            off = ((size_t)b * (P_LEN / 2) + l) * D4 + d4;
        } else {
            off = half_elems4 + ((size_t)b * (P_LEN / 2) + (l - P_LEN / 2)) * D4 + d4;
        }
        out4[off] = acc;
    }
}

// ---------------------------------------------------------------------------
// Kernel 4: pass-through copy of x_block (float4)
// ---------------------------------------------------------------------------
__global__ void copy_kernel(const float4* __restrict__ src,
                            float4* __restrict__ dst,
                            long long n4) {
    long long i = (long long)blockIdx.x * blockDim.x + threadIdx.x;
    if (i < n4) dst[i] = src[i];
}

extern "C" void kernel_launch(void* const* d_in, const int* in_sizes, int n_in,
                              void* d_out, int out_size) {
    const float* x_querry = (const float*)d_in[0];
    const float* x_block  = (const float*)d_in[1];
    const float* e_a      = (const float*)d_in[2];
    const float* e_p      = (const float*)d_in[3];
    // d_in[4] = idx (unused by reference)
    const int*   task_id  = (const int*)d_in[5];

    float* out = (float*)d_out;

    // (1) diag — sized for max task_end=POOL, guarded inside
    {
        const int total = POOL * EMB_D;
        diag_kernel<<<(total + 255) / 256, 256>>>(e_p, task_id);
    }
    // (2) sim — grid covers max, guarded inside
    {
        dim3 grid(BATCH, POOL);
        sim_kernel<<<grid, 256>>>(x_querry, e_a, task_id);
    }
    // (3) int_pmt -> key/value halves of the output
    pmt_kernel<<<BATCH, 256>>>(e_p, task_id, out);

    // (4) x_block pass-through into the tail of the output
    {
        const long long n_xblock = (long long)BATCH * NBLK * EMB_D;  // 77,414,400
        const long long n4 = n_xblock / 4;                           // divisible
        float* dst = out + (size_t)2 * BATCH * (P_LEN / 2) * EMB_D;  // after key+value
        copy_kernel<<<(unsigned)((n4 + 255) / 256), 256>>>(
            (const float4*)x_block, (float4*)dst, n4);
    }
}

// round 2
// speedup vs baseline: 1.1847x; 1.1847x over previous
#include <cuda_runtime.h>
#include <math.h>

#define POOL    100
#define N_TASKS  10
#define P_LEN     8
#define EMB_D   768
#define BATCH   512
#define NBLK    197

#define D4      (EMB_D / 4)          // 192
#define N_XBLOCK ((long long)BATCH * NBLK * EMB_D)   // 77,414,400
#define N4      (N_XBLOCK / 4)       // 19,353,600
#define COPY_BLOCKS ((int)((N4 + 255) / 256))        // 75,600

// ---------------------------------------------------------------------------
// One fused kernel.
//   blocks [0, BATCH)              : per-b sim + pmt (diag computed on the fly)
//   blocks [BATCH, BATCH+COPY_BLOCKS): float4 pass-through copy of x_block
// ---------------------------------------------------------------------------
__global__ void __launch_bounds__(256)
fused_kernel(const float* __restrict__ x_querry,
             const float4* __restrict__ x_block4,
             const float* __restrict__ e_a,
             const float* __restrict__ e_p,
             const int* __restrict__ task_id,
             float* __restrict__ out) {

    if (blockIdx.x >= BATCH) {
        // ------------------ pass-through copy ------------------
        long long i = (long long)(blockIdx.x - BATCH) * 256 + threadIdx.x;
        float4* dst = (float4*)(out + (size_t)2 * BATCH * (P_LEN / 2) * EMB_D);
        if (i < N4) dst[i] = x_block4[i];
        return;
    }

    // ------------------ per-b sim + pmt ------------------
    const int te = (task_id[0] + 1) * (POOL / N_TASKS);
    const int b = blockIdx.x;
    const int wid = threadIdx.x >> 5;
    const int lid = threadIdx.x & 31;

    __shared__ float sim_s[POOL];

    // one warp per k; warps stride over k
    for (int k = wid; k < te; k += 8) {
        const float4* __restrict__ x4 =
            (const float4*)(x_querry + ((size_t)b * POOL + (POOL - te + k)) * EMB_D);
        const float4* __restrict__ ea4 = (const float4*)(e_a + (size_t)k * EMB_D);
        const float4* __restrict__ ep4 = (const float4*)(e_p + (size_t)k * P_LEN * EMB_D);

        float sa = 0.f, sad = 0.f, sadd = 0.f;
        for (int d = lid; d < D4; d += 32) {
            float4 xv = x4[d];
            float4 ev = ea4[d];
            // diag on the fly: dd = sum_l e_p[k][l][d]^2
            float ddx = 0.f, ddy = 0.f, ddz = 0.f, ddw = 0.f;
#pragma unroll
            for (int l = 0; l < P_LEN; ++l) {
                float4 p = ep4[l * D4 + d];
                ddx = fmaf(p.x, p.x, ddx);
                ddy = fmaf(p.y, p.y, ddy);
                ddz = fmaf(p.z, p.z, ddz);
                ddw = fmaf(p.w, p.w, ddw);
            }
            float a, a2;
            a = xv.x * ev.x; a2 = a * a; sa += a2; sad = fmaf(a2, ddx, sad); sadd = fmaf(a2 * ddx, ddx, sadd);
            a = xv.y * ev.y; a2 = a * a; sa += a2; sad = fmaf(a2, ddy, sad); sadd = fmaf(a2 * ddy, ddy, sadd);
            a = xv.z * ev.z; a2 = a * a; sa += a2; sad = fmaf(a2, ddz, sad); sadd = fmaf(a2 * ddz, ddz, sadd);
            a = xv.w * ev.w; a2 = a * a; sa += a2; sad = fmaf(a2, ddw, sad); sadd = fmaf(a2 * ddw, ddw, sadd);
        }
#pragma unroll
        for (int off = 16; off > 0; off >>= 1) {
            sa   += __shfl_down_sync(0xffffffffu, sa,   off);
            sad  += __shfl_down_sync(0xffffffffu, sad,  off);
            sadd += __shfl_down_sync(0xffffffffu, sadd, off);
        }
        if (lid == 0) {
            float na  = fmaxf(sqrtf(sa),   1e-12f);
            float nad = fmaxf(sqrtf(sadd), 1e-12f);
            sim_s[k] = sad / (na * nad);
        }
    }
    __syncthreads();

    // pmt: int_pmt[b,l,:] = sum_k sim_s[k] * e_p[k,l,:] ; split key/value
    const int NV = P_LEN * D4;           // 1536 float4
    const float4* __restrict__ ep4 = (const float4*)e_p;
    float4* __restrict__ out4 = (float4*)out;
    const size_t half4 = (size_t)BATCH * (P_LEN / 2) * D4;

    for (int v = threadIdx.x; v < NV; v += blockDim.x) {
        float4 acc = make_float4(0.f, 0.f, 0.f, 0.f);
        for (int k = 0; k < te; ++k) {
            const float s = sim_s[k];
            const float4 e = ep4[(size_t)k * NV + v];
            acc.x = fmaf(s, e.x, acc.x);
            acc.y = fmaf(s, e.y, acc.y);
            acc.z = fmaf(s, e.z, acc.z);
            acc.w = fmaf(s, e.w, acc.w);
        }
        const int l  = v / D4;
        const int d4 = v - l * D4;
        size_t off;
        if (l < P_LEN / 2) {
            off = ((size_t)b * (P_LEN / 2) + l) * D4 + d4;
        } else {
            off = half4 + ((size_t)b * (P_LEN / 2) + (l - P_LEN / 2)) * D4 + d4;
        }
        out4[off] = acc;
    }
}

extern "C" void kernel_launch(void* const* d_in, const int* in_sizes, int n_in,
                              void* d_out, int out_size) {
    const float* x_querry = (const float*)d_in[0];
    const float* x_block  = (const float*)d_in[1];
    const float* e_a      = (const float*)d_in[2];
    const float* e_p      = (const float*)d_in[3];
    const int*   task_id  = (const int*)d_in[5];

    float* out = (float*)d_out;

    fused_kernel<<<BATCH + COPY_BLOCKS, 256>>>(
        x_querry, (const float4*)x_block, e_a, e_p, task_id, out);
}

// round 3
// speedup vs baseline: 1.4300x; 1.2070x over previous
#include <cuda_runtime.h>
#include <math.h>

#define POOL    100
#define N_TASKS  10
#define P_LEN     8
#define EMB_D   768
#define BATCH   512
#define NBLK    197

#define D4      (EMB_D / 4)          // 192
#define N_XBLOCK ((long long)BATCH * NBLK * EMB_D)   // 77,414,400
#define N4      (N_XBLOCK / 4)       // 19,353,600 float4
#define V4_PER_THREAD 4
#define COPY_BLOCKS ((int)(N4 / (256 * V4_PER_THREAD)))  // 18,900 exact

// ---------------------------------------------------------------------------
// One fused kernel, register-capped so the copy path runs at full occupancy.
//   blocks [0, BATCH)                 : per-b sim + pmt (diag on the fly)
//   blocks [BATCH, BATCH+COPY_BLOCKS) : float4 x4 streaming copy of x_block
// ---------------------------------------------------------------------------
__global__ void __launch_bounds__(256, 8)
fused_kernel(const float* __restrict__ x_querry,
             const float4* __restrict__ x_block4,
             const float* __restrict__ e_a,
             const float* __restrict__ e_p,
             const int* __restrict__ task_id,
             float* __restrict__ out) {

    if (blockIdx.x >= BATCH) {
        // ------------------ streaming pass-through copy ------------------
        // 4 float4 per thread; loads issued before stores (MLP=4); .cs hints
        float4* dst = (float4*)(out + (size_t)2 * BATCH * (P_LEN / 2) * EMB_D);
        const long long base =
            (long long)(blockIdx.x - BATCH) * (256 * V4_PER_THREAD) + threadIdx.x;
        float4 v0 = __ldcs(&x_block4[base +   0]);
        float4 v1 = __ldcs(&x_block4[base + 256]);
        float4 v2 = __ldcs(&x_block4[base + 512]);
        float4 v3 = __ldcs(&x_block4[base + 768]);
        __stcs(&dst[base +   0], v0);
        __stcs(&dst[base + 256], v1);
        __stcs(&dst[base + 512], v2);
        __stcs(&dst[base + 768], v3);
        return;
    }

    // ------------------ per-b sim + pmt ------------------
    const int te = (task_id[0] + 1) * (POOL / N_TASKS);
    const int b = blockIdx.x;
    const int wid = threadIdx.x >> 5;
    const int lid = threadIdx.x & 31;

    __shared__ float sim_s[POOL];

    // one warp per k; warps stride over k
    for (int k = wid; k < te; k += 8) {
        const float4* __restrict__ x4 =
            (const float4*)(x_querry + ((size_t)b * POOL + (POOL - te + k)) * EMB_D);
        const float4* __restrict__ ea4 = (const float4*)(e_a + (size_t)k * EMB_D);
        const float4* __restrict__ ep4 = (const float4*)(e_p + (size_t)k * P_LEN * EMB_D);

        float sa = 0.f, sad = 0.f, sadd = 0.f;
        for (int d = lid; d < D4; d += 32) {
            float4 xv = x4[d];
            float4 ev = ea4[d];
            float ddx = 0.f, ddy = 0.f, ddz = 0.f, ddw = 0.f;
#pragma unroll
            for (int l = 0; l < P_LEN; ++l) {
                float4 p = ep4[l * D4 + d];
                ddx = fmaf(p.x, p.x, ddx);
                ddy = fmaf(p.y, p.y, ddy);
                ddz = fmaf(p.z, p.z, ddz);
                ddw = fmaf(p.w, p.w, ddw);
            }
            float a, a2;
            a = xv.x * ev.x; a2 = a * a; sa += a2; sad = fmaf(a2, ddx, sad); sadd = fmaf(a2 * ddx, ddx, sadd);
            a = xv.y * ev.y; a2 = a * a; sa += a2; sad = fmaf(a2, ddy, sad); sadd = fmaf(a2 * ddy, ddy, sadd);
            a = xv.z * ev.z; a2 = a * a; sa += a2; sad = fmaf(a2, ddz, sad); sadd = fmaf(a2 * ddz, ddz, sadd);
            a = xv.w * ev.w; a2 = a * a; sa += a2; sad = fmaf(a2, ddw, sad); sadd = fmaf(a2 * ddw, ddw, sadd);
        }
#pragma unroll
        for (int off = 16; off > 0; off >>= 1) {
            sa   += __shfl_down_sync(0xffffffffu, sa,   off);
            sad  += __shfl_down_sync(0xffffffffu, sad,  off);
            sadd += __shfl_down_sync(0xffffffffu, sadd, off);
        }
        if (lid == 0) {
            float na  = fmaxf(sqrtf(sa),   1e-12f);
            float nad = fmaxf(sqrtf(sadd), 1e-12f);
            sim_s[k] = sad / (na * nad);
        }
    }
    __syncthreads();

    // pmt: int_pmt[b,l,:] = sum_k sim_s[k] * e_p[k,l,:] ; split key/value
    const int NV = P_LEN * D4;           // 1536 float4
    const float4* __restrict__ ep4 = (const float4*)e_p;
    float4* __restrict__ out4 = (float4*)out;
    const size_t half4 = (size_t)BATCH * (P_LEN / 2) * D4;

    for (int v = threadIdx.x; v < NV; v += blockDim.x) {
        float4 acc = make_float4(0.f, 0.f, 0.f, 0.f);
        for (int k = 0; k < te; ++k) {
            const float s = sim_s[k];
            const float4 e = ep4[(size_t)k * NV + v];
            acc.x = fmaf(s, e.x, acc.x);
            acc.y = fmaf(s, e.y, acc.y);
            acc.z = fmaf(s, e.z, acc.z);
            acc.w = fmaf(s, e.w, acc.w);
        }
        const int l  = v / D4;
        const int d4 = v - l * D4;
        size_t off;
        if (l < P_LEN / 2) {
            off = ((size_t)b * (P_LEN / 2) + l) * D4 + d4;
        } else {
            off = half4 + ((size_t)b * (P_LEN / 2) + (l - P_LEN / 2)) * D4 + d4;
        }
        out4[off] = acc;
    }
}

extern "C" void kernel_launch(void* const* d_in, const int* in_sizes, int n_in,
                              void* d_out, int out_size) {
    const float* x_querry = (const float*)d_in[0];
    const float* x_block  = (const float*)d_in[1];
    const float* e_a      = (const float*)d_in[2];
    const float* e_p      = (const float*)d_in[3];
    const int*   task_id  = (const int*)d_in[5];

    float* out = (float*)d_out;

    fused_kernel<<<BATCH + COPY_BLOCKS, 256>>>(
        x_querry, (const float4*)x_block, e_a, e_p, task_id, out);
}